// round 14
// baseline (speedup 1.0000x reference)
#include <cuda_runtime.h>
#include <cuda_fp16.h>
#include <cstdint>

// ---------------- problem constants ----------------
#define BROWS 10240          // B*N = 2048*5
#define HID   2048
#define OUTD  512
#define PLANE ((size_t)BROWS * HID)
#define OPLANE ((size_t)BROWS * OUTD)

// ---------------- persistent device scratch ----------------
// 5 DFT planes: [0]=X0, [1]=X2, [2]=Xs(=Xr+Xi), [3]=Xr, [4]=Xi
__device__ __align__(1024) __half g_act1[5 * PLANE];
__device__ __align__(1024) __half g_pre2[5 * PLANE];
__device__ __align__(1024) __half g_act2[5 * PLANE];
__device__ __align__(1024) __half g_w2h[(size_t)5 * HID * HID];
__device__ __align__(1024) __half g_w3h[(size_t)5 * OUTD * HID];
__device__ __align__(1024) __half g_out3h[5 * OPLANE];   // layer3 GEMM out (fp16)
__device__ int g_cnt3[320];                              // per-tile arrival counters (zero-init)

// ---------------- orbit table ----------------
__constant__ int c_orbit[28] = {
    12, 0, 1, 2, 5, 6, 7,
    12, 4, 9, 14, 3, 8, 13,
    12, 24, 23, 22, 19, 18, 17,
    12, 20, 15, 10, 21, 16, 11
};

// ---------------- PTX helpers (baseline PTX only) ----------------
__device__ __forceinline__ uint32_t smem_u32(const void* p) {
    uint32_t a;
    asm("{ .reg .u64 t; cvta.to.shared.u64 t, %1; cvt.u32.u64 %0, t; }" : "=r"(a) : "l"(p));
    return a;
}
__device__ __forceinline__ void cp16(uint32_t d, const void* g) {
    asm volatile("cp.async.cg.shared.global [%0],[%1],16;\n" ::"r"(d), "l"(g));
}
#define LDSM4(r0, r1, r2, r3, addr) \
    asm volatile("ldmatrix.sync.aligned.m8n8.x4.shared.b16 {%0,%1,%2,%3},[%4];" \
                 : "=r"(r0), "=r"(r1), "=r"(r2), "=r"(r3) : "r"(addr))

__device__ __forceinline__ void mma16816(float* c, const uint32_t* a, uint32_t b0, uint32_t b1) {
    asm volatile(
        "mma.sync.aligned.m16n8k16.row.col.f32.f16.f16.f32 "
        "{%0,%1,%2,%3},{%4,%5,%6,%7},{%8,%9},{%0,%1,%2,%3};"
        : "+f"(c[0]), "+f"(c[1]), "+f"(c[2]), "+f"(c[3])
        : "r"(a[0]), "r"(a[1]), "r"(a[2]), "r"(a[3]), "r"(b0), "r"(b1));
}

// ---------------- weight combo prep ----------------
__global__ void wprep_kernel(const float* __restrict__ w2, const float* __restrict__ w3) {
    const size_t S2 = (size_t)HID * HID;
    const size_t S3 = (size_t)OUTD * HID;
    const size_t stride = (size_t)gridDim.x * blockDim.x;
    for (size_t i = (size_t)blockIdx.x * blockDim.x + threadIdx.x; i < S2; i += stride) {
        float a = w2[i], b = w2[S2 + i], c = w2[2 * S2 + i], d = w2[3 * S2 + i];
        g_w2h[0 * S2 + i] = __float2half(a + b + c + d);
        g_w2h[1 * S2 + i] = __float2half(a - b + c - d);
        g_w2h[2 * S2 + i] = __float2half(a - c);
        g_w2h[3 * S2 + i] = __float2half(-a + b + c - d);
        g_w2h[4 * S2 + i] = __float2half(a + b - c - d);
    }
    for (size_t i = (size_t)blockIdx.x * blockDim.x + threadIdx.x; i < S3; i += stride) {
        float a = w3[i], b = w3[S3 + i], c = w3[2 * S3 + i], d = w3[3 * S3 + i];
        g_w3h[0 * S3 + i] = __float2half(a + b + c + d);
        g_w3h[1 * S3 + i] = __float2half(a - b + c - d);
        g_w3h[2 * S3 + i] = __float2half(a - c);
        g_w3h[3 * S3 + i] = __float2half(-a + b + c - d);
        g_w3h[4 * S3 + i] = __float2half(a + b - c - d);
    }
}

// ---------------- layer 1: 16 rows per CTA ----------------
__global__ void layer1_kernel(const float* __restrict__ ins,
                              const float* __restrict__ w1,
                              const float* __restrict__ b1) {
    __shared__ float patch[16][25];
    __shared__ float feat[16][4][7];
    const int row0 = blockIdx.x * 16;
    const int t = threadIdx.x;

    for (int idx = t; idx < 400; idx += 256)
        patch[idx / 25][idx % 25] = ins[(size_t)row0 * 25 + idx];
    __syncthreads();
    for (int idx = t; idx < 448; idx += 256) {
        const int r = idx / 28, k = idx % 28;
        feat[r][k / 7][k % 7] = patch[r][c_orbit[k]];
    }
    __syncthreads();

    for (int i = t; i < HID; i += 256) {
        const float bv = b1[i];
        float w[4][7];
        #pragma unroll
        for (int d = 0; d < 4; d++)
            #pragma unroll
            for (int j = 0; j < 7; j++)
                w[d][j] = w1[((size_t)d * HID + i) * 7 + j];

        for (int r = 0; r < 16; r++) {
            float acc[4] = {bv, bv, bv, bv};
            #pragma unroll
            for (int d = 0; d < 4; d++) {
                #pragma unroll
                for (int g = 0; g < 4; g++) {
                    const float* f = feat[r][(g + d) & 3];
                    float a = 0.f;
                    #pragma unroll
                    for (int j = 0; j < 7; j++) a += w[d][j] * f[j];
                    acc[g] += a;
                }
            }
            const float r0 = fmaxf(acc[0], 0.f), r1 = fmaxf(acc[1], 0.f);
            const float r2 = fmaxf(acc[2], 0.f), r3 = fmaxf(acc[3], 0.f);
            const float xr = r0 - r2, xi = r3 - r1;
            const size_t off = (size_t)(row0 + r) * HID + i;
            g_act1[0 * PLANE + off] = __float2half(r0 + r1 + r2 + r3);
            g_act1[1 * PLANE + off] = __float2half(r0 - r1 + r2 - r3);
            g_act1[2 * PLANE + off] = __float2half(xr + xi);
            g_act1[3 * PLANE + off] = __float2half(xr);
            g_act1[4 * PLANE + off] = __float2half(xi);
        }
    }
}

// ---------------- batched GEMM: C[j] = A[j] @ B[j]^T  (j = 0..4) ----------------
// R13-exact mainloop (frozen). R14: for LAYER==3, the last CTA per output tile
// fuses the inverse-DFT + bias combine (threadFence-reduction pattern).
static constexpr int GEMM_SMEM = 3 * 16384 * 2;  // 98304

template <int LAYER>
__global__ __launch_bounds__(256, 2)
void gemm_kernel(const float* __restrict__ b3, float* __restrict__ out) {
    constexpr int BK = 64;
    constexpr int KT = HID / BK;  // 32
    constexpr size_t BSTRIDE = (LAYER == 2) ? (size_t)HID * HID : (size_t)OUTD * HID;
    constexpr int CP = (LAYER == 2) ? HID : OUTD;

    extern __shared__ char smem[];
    const uint32_t sA = smem_u32(smem);            // [3][16KB]
    const uint32_t sB = sA + 3 * 16384;            // [3][16KB]

    const int tid = threadIdx.x;
    const int j = blockIdx.z;
    const int brow = blockIdx.y * 128;
    const int bcol = blockIdx.x * 128;

    const __half* Aall = (LAYER == 2) ? g_act1 : g_act2;
    const __half* Ball = (LAYER == 2) ? g_w2h : g_w3h;
    const char* Ag = (const char*)(Aall + (size_t)j * PLANE + (size_t)brow * HID);
    const char* Bg = (const char*)(Ball + (size_t)j * BSTRIDE + (size_t)bcol * HID);

    // loader mapping: thread t -> 16B group lg of rows lr0 + 32*i
    const int lg = tid & 7;
    const int lr0 = tid >> 3;

    auto issue = [&](int st, int kt) {
        const uint32_t dA = sA + st * 16384, dB = sB + st * 16384;
        const char* gA = Ag + (size_t)kt * 128;
        const char* gB = Bg + (size_t)kt * 128;
        #pragma unroll
        for (int i = 0; i < 4; i++) {
            const int r = lr0 + i * 32;
            const uint32_t ph = (uint32_t)r * 128 + (uint32_t)((lg ^ (r & 7)) * 16);
            cp16(dA + ph, gA + (size_t)r * (HID * 2) + lg * 16);
            cp16(dB + ph, gB + (size_t)r * (HID * 2) + lg * 16);
        }
        asm volatile("cp.async.commit_group;\n");
    };

    issue(0, 0);
    issue(1, 1);

    const int warp = tid >> 5, lane = tid & 31;
    const int wm = (warp >> 2) * 64;   // 2 warp rows
    const int wn = (warp & 3) * 32;    // 4 warp cols
    const int rl = (lane & 7) + (((lane >> 3) & 1) << 3);  // 0..15
    const int hs = (lane >> 4) & 1;
    const int sw = lane & 7;

    float acc[4][4][4];
    #pragma unroll
    for (int m = 0; m < 4; m++)
        #pragma unroll
        for (int n = 0; n < 4; n++)
            #pragma unroll
            for (int q = 0; q < 4; q++) acc[m][n][q] = 0.f;

    for (int kt = 0; kt < KT; kt++) {
        asm volatile("cp.async.wait_group 1;\n");
        __syncthreads();   // fences prev-iter readers of stage (kt+2)%3

        const int st = kt % 3;
        const uint32_t aBase = sA + st * 16384 + (uint32_t)(wm + rl) * 128;
        const uint32_t bBase = sB + st * 16384 + (uint32_t)(wn + rl) * 128;

        // double-buffered fragments across kk
        uint32_t af[2][4][4], bf[2][2][4];

        // preload kk = 0
        {
            const uint32_t goff = (uint32_t)((hs ^ sw) * 16);
            #pragma unroll
            for (int n2 = 0; n2 < 2; n2++)
                LDSM4(bf[0][n2][0], bf[0][n2][1], bf[0][n2][2], bf[0][n2][3],
                      bBase + n2 * 16 * 128 + goff);
            #pragma unroll
            for (int m = 0; m < 4; m++)
                LDSM4(af[0][m][0], af[0][m][1], af[0][m][2], af[0][m][3],
                      aBase + m * 16 * 128 + goff);
        }

        #pragma unroll
        for (int kk = 0; kk < 4; kk++) {
            const int cur = kk & 1, nxt = cur ^ 1;
            // prefetch kk+1 fragments BEFORE this kk's MMAs
            if (kk < 3) {
                const uint32_t goff = (uint32_t)((((kk + 1) * 2 + hs) ^ sw) * 16);
                #pragma unroll
                for (int n2 = 0; n2 < 2; n2++)
                    LDSM4(bf[nxt][n2][0], bf[nxt][n2][1], bf[nxt][n2][2], bf[nxt][n2][3],
                          bBase + n2 * 16 * 128 + goff);
                #pragma unroll
                for (int m = 0; m < 4; m++)
                    LDSM4(af[nxt][m][0], af[nxt][m][1], af[nxt][m][2], af[nxt][m][3],
                          aBase + m * 16 * 128 + goff);
            }
            #pragma unroll
            for (int m = 0; m < 4; m++) {
                #pragma unroll
                for (int n2 = 0; n2 < 2; n2++) {
                    mma16816(acc[m][n2 * 2 + 0], af[cur][m], bf[cur][n2][0], bf[cur][n2][2]);
                    mma16816(acc[m][n2 * 2 + 1], af[cur][m], bf[cur][n2][1], bf[cur][n2][3]);
                }
            }
            // combined issue+commit right after first kk block (R6-proven placement)
            if (kk == 0) {
                if (kt + 2 < KT) issue((kt + 2) % 3, kt + 2);
                else asm volatile("cp.async.commit_group;\n");
            }
        }
    }

    // ---- epilogue: stage C (fp16) through smem, then coalesced 16-B stores ----
    asm volatile("cp.async.wait_group 0;\n");   // drain tail copies into stage slots
    __syncthreads();                             // all warps done with mainloop smem

    const int r0 = lane >> 2, cql = (lane & 3) * 2;
    constexpr int PT = 136;                      // halves; 16B-aligned rows, +4 bank shift/row
    __half* sC = (__half*)smem;
    #pragma unroll
    for (int m = 0; m < 4; m++) {
        #pragma unroll
        for (int jn = 0; jn < 4; jn++) {
            const int rr = wm + m * 16 + r0;
            const int cc = wn + (jn >> 1) * 16 + (jn & 1) * 8 + cql;
            *(__half2*)&sC[(size_t)rr * PT + cc] =
                __floats2half2_rn(acc[m][jn][0], acc[m][jn][1]);
            *(__half2*)&sC[(size_t)(rr + 8) * PT + cc] =
                __floats2half2_rn(acc[m][jn][2], acc[m][jn][3]);
        }
    }
    __syncthreads();
    __half* C = (LAYER == 2) ? (g_pre2 + (size_t)j * PLANE)
                             : (g_out3h + (size_t)j * OPLANE);
    #pragma unroll
    for (int i = 0; i < 8; i++) {                // 2048 chunks of 16B / 256 thr
        const int idx = tid + i * 256;
        const int rr = idx >> 4;
        const int cc = (idx & 15) * 8;
        uint4 v = *(const uint4*)&sC[(size_t)rr * PT + cc];
        *(uint4*)&C[(size_t)(brow + rr) * CP + bcol + cc] = v;
    }

    // ---- LAYER 3 only: last CTA per tile fuses inverse DFT + bias ----
    if (LAYER == 3) {
        __threadfence();       // my plane-tile stores visible device-wide
        __syncthreads();       // all threads' stores fenced before the atomic
        __shared__ int amLast;
        const int cidx = blockIdx.y * 4 + blockIdx.x;
        if (tid == 0) {
            int old = atomicAdd(&g_cnt3[cidx], 1);
            amLast = (old == 4);
            if (old == 4) atomicExch(&g_cnt3[cidx], 0);   // reset for next replay
        }
        __syncthreads();
        if (amLast) {
            // all 5 planes of this (brow, bcol) tile are complete and visible
            #pragma unroll
            for (int i = 0; i < 8; i++) {
                const int idx = tid + i * 256;     // 128 rows x 16 col-groups
                const int rr = idx >> 4;
                const int cc = (idx & 15) * 8;
                const size_t poff = (size_t)(brow + rr) * OUTD + bcol + cc;

                float P[5][8];
                #pragma unroll
                for (int jp = 0; jp < 5; jp++) {
                    uint4 v = *(const uint4*)(g_out3h + (size_t)jp * OPLANE + poff);
                    const __half2* h = (const __half2*)&v;
                    #pragma unroll
                    for (int k = 0; k < 4; k++) {
                        float2 f = __half22float2(h[k]);
                        P[jp][2 * k] = f.x;
                        P[jp][2 * k + 1] = f.y;
                    }
                }
                float bb[8];
                *(float4*)&bb[0] = *(const float4*)&b3[bcol + cc];
                *(float4*)&bb[4] = *(const float4*)&b3[bcol + cc + 4];

                float o[4][8];
                #pragma unroll
                for (int k = 0; k < 8; k++) {
                    const float yr = P[2][k] - P[4][k];
                    const float yi = P[2][k] + P[3][k];
                    const float e = P[0][k] + P[1][k], od = P[0][k] - P[1][k];
                    o[0][k] = 0.25f * (e + 2.f * yr) + bb[k];
                    o[1][k] = 0.25f * (od - 2.f * yi) + bb[k];
                    o[2][k] = 0.25f * (e - 2.f * yr) + bb[k];
                    o[3][k] = 0.25f * (od + 2.f * yi) + bb[k];
                }
                float* dst = out + (size_t)(brow + rr) * 2048 + bcol + cc;
                #pragma unroll
                for (int g = 0; g < 4; g++) {
                    *(float4*)&dst[(size_t)g * OUTD + 0] = *(const float4*)&o[g][0];
                    *(float4*)&dst[(size_t)g * OUTD + 4] = *(const float4*)&o[g][4];
                }
            }
        }
    }
}

// ---------------- inverse DFT + bias + LN + relu + forward DFT ----------------
__global__ void ln_tf_kernel(const float* __restrict__ b2,
                             const float* __restrict__ lng,
                             const float* __restrict__ lnb) {
    const size_t rf = blockIdx.x;
    const int t = threadIdx.x;
    const size_t off = rf * HID;
    const int c0 = t * 8;

    float P[5][8];
    #pragma unroll
    for (int jp = 0; jp < 5; jp++) {
        float4 v = *((const float4*)(g_pre2 + jp * PLANE + off) + t);
        const __half2* h = (const __half2*)&v;
        #pragma unroll
        for (int k = 0; k < 4; k++) {
            float2 f = __half22float2(h[k]);
            P[jp][2 * k] = f.x;
            P[jp][2 * k + 1] = f.y;
        }
    }

    float bb[8];
    *(float4*)&bb[0] = *(const float4*)&b2[c0];
    *(float4*)&bb[4] = *(const float4*)&b2[c0 + 4];

    float y[4][8];
    float s[4] = {0.f, 0.f, 0.f, 0.f}, q[4] = {0.f, 0.f, 0.f, 0.f};
    #pragma unroll
    for (int k = 0; k < 8; k++) {
        const float yr = P[2][k] - P[4][k];
        const float yi = P[2][k] + P[3][k];
        const float e = P[0][k] + P[1][k], o = P[0][k] - P[1][k];
        y[0][k] = 0.25f * (e + 2.f * yr) + bb[k];
        y[1][k] = 0.25f * (o - 2.f * yi) + bb[k];
        y[2][k] = 0.25f * (e - 2.f * yr) + bb[k];
        y[3][k] = 0.25f * (o + 2.f * yi) + bb[k];
        #pragma unroll
        for (int g = 0; g < 4; g++) { s[g] += y[g][k]; q[g] += y[g][k] * y[g][k]; }
    }

    __shared__ float ss[4][8], qq[4][8];
    const int warp = t >> 5, lane = t & 31;
    #pragma unroll
    for (int g = 0; g < 4; g++) {
        #pragma unroll
        for (int o = 16; o > 0; o >>= 1) {
            s[g] += __shfl_down_sync(0xffffffffu, s[g], o);
            q[g] += __shfl_down_sync(0xffffffffu, q[g], o);
        }
        if (lane == 0) { ss[g][warp] = s[g]; qq[g][warp] = q[g]; }
    }
    __syncthreads();
    __shared__ float mean[4], rstd[4];
    if (t < 4) {
        float a = 0.f, b = 0.f;
        #pragma unroll
        for (int w = 0; w < 8; w++) { a += ss[t][w]; b += qq[t][w]; }
        const float m = a * (1.f / HID);
        mean[t] = m;
        rstd[t] = rsqrtf(b * (1.f / HID) - m * m + 1e-5f);
    }
    __syncthreads();

    float gv[8], bv[8];
    *(float4*)&gv[0] = *(const float4*)&lng[c0];
    *(float4*)&gv[4] = *(const float4*)&lng[c0 + 4];
    *(float4*)&bv[0] = *(const float4*)&lnb[c0];
    *(float4*)&bv[4] = *(const float4*)&lnb[c0 + 4];

    float r[4][8];
    #pragma unroll
    for (int k = 0; k < 8; k++) {
        #pragma unroll
        for (int g = 0; g < 4; g++)
            r[g][k] = fmaxf((y[g][k] - mean[g]) * rstd[g] * gv[k] + bv[k], 0.f);
    }

    float Z[5][8];
    #pragma unroll
    for (int k = 0; k < 8; k++) {
        const float zr = r[0][k] - r[2][k], zi = r[3][k] - r[1][k];
        Z[0][k] = r[0][k] + r[1][k] + r[2][k] + r[3][k];
        Z[1][k] = r[0][k] - r[1][k] + r[2][k] - r[3][k];
        Z[2][k] = zr + zi;
        Z[3][k] = zr;
        Z[4][k] = zi;
    }
    #pragma unroll
    for (int jp = 0; jp < 5; jp++) {
        float4 v;
        __half2* h = (__half2*)&v;
        #pragma unroll
        for (int k = 0; k < 4; k++)
            h[k] = __floats2half2_rn(Z[jp][2 * k], Z[jp][2 * k + 1]);
        *((float4*)(g_act2 + jp * PLANE + off) + t) = v;
    }
}

// ---------------- launch ----------------
extern "C" void kernel_launch(void* const* d_in, const int* in_sizes, int n_in,
                              void* d_out, int out_size) {
    const float* ins = (const float*)d_in[0];
    const float* w1 = (const float*)d_in[1];
    const float* b1 = (const float*)d_in[2];
    const float* w2 = (const float*)d_in[3];
    const float* b2 = (const float*)d_in[4];
    const float* w3 = (const float*)d_in[5];
    const float* b3 = (const float*)d_in[6];
    const float* lng = (const float*)d_in[7];
    const float* lnb = (const float*)d_in[8];
    float* out = (float*)d_out;

    cudaFuncSetAttribute(gemm_kernel<2>, cudaFuncAttributeMaxDynamicSharedMemorySize, GEMM_SMEM);
    cudaFuncSetAttribute(gemm_kernel<3>, cudaFuncAttributeMaxDynamicSharedMemorySize, GEMM_SMEM);

    wprep_kernel<<<2048, 256>>>(w2, w3);
    layer1_kernel<<<BROWS / 16, 256>>>(ins, w1, b1);

    {
        dim3 grid(HID / 128, BROWS / 128, 5);   // (16, 80, 5)
        gemm_kernel<2><<<grid, 256, GEMM_SMEM>>>(nullptr, nullptr);
    }
    ln_tf_kernel<<<BROWS, 256>>>(b2, lng, lnb);
    {
        dim3 grid(OUTD / 128, BROWS / 128, 5);  // (4, 80, 5)
        gemm_kernel<3><<<grid, 256, GEMM_SMEM>>>(b3, out);
    }
}

// round 15
// speedup vs baseline: 1.0227x; 1.0227x over previous
#include <cuda_runtime.h>
#include <cuda_fp16.h>
#include <cstdint>

// ---------------- problem constants ----------------
#define BROWS 10240          // B*N = 2048*5
#define HID   2048
#define OUTD  512
#define PLANE ((size_t)BROWS * HID)
#define OPLANE ((size_t)BROWS * OUTD)

// ---------------- persistent device scratch ----------------
// 5 DFT planes: [0]=X0, [1]=X2, [2]=Xs(=Xr+Xi), [3]=Xr, [4]=Xi
__device__ __align__(1024) __half g_act1[5 * PLANE];
__device__ __align__(1024) __half g_pre2[5 * PLANE];
__device__ __align__(1024) __half g_act2[5 * PLANE];
__device__ __align__(1024) __half g_w2h[(size_t)5 * HID * HID];
__device__ __align__(1024) __half g_w3h[(size_t)5 * OUTD * HID];
__device__ __align__(1024) __half g_out3h[5 * OPLANE];   // layer3 GEMM out (fp16)
__device__ __align__(1024) float  g_w1t[4 * 7 * HID];    // w1 transposed [d][j][i]

// ---------------- orbit table ----------------
__constant__ int c_orbit[28] = {
    12, 0, 1, 2, 5, 6, 7,
    12, 4, 9, 14, 3, 8, 13,
    12, 24, 23, 22, 19, 18, 17,
    12, 20, 15, 10, 21, 16, 11
};

// ---------------- PTX helpers (baseline PTX only) ----------------
__device__ __forceinline__ uint32_t smem_u32(const void* p) {
    uint32_t a;
    asm("{ .reg .u64 t; cvta.to.shared.u64 t, %1; cvt.u32.u64 %0, t; }" : "=r"(a) : "l"(p));
    return a;
}
__device__ __forceinline__ void cp16(uint32_t d, const void* g) {
    asm volatile("cp.async.cg.shared.global [%0],[%1],16;\n" ::"r"(d), "l"(g));
}
#define LDSM4(r0, r1, r2, r3, addr) \
    asm volatile("ldmatrix.sync.aligned.m8n8.x4.shared.b16 {%0,%1,%2,%3},[%4];" \
                 : "=r"(r0), "=r"(r1), "=r"(r2), "=r"(r3) : "r"(addr))

__device__ __forceinline__ void mma16816(float* c, const uint32_t* a, uint32_t b0, uint32_t b1) {
    asm volatile(
        "mma.sync.aligned.m16n8k16.row.col.f32.f16.f16.f32 "
        "{%0,%1,%2,%3},{%4,%5,%6,%7},{%8,%9},{%0,%1,%2,%3};"
        : "+f"(c[0]), "+f"(c[1]), "+f"(c[2]), "+f"(c[3])
        : "r"(a[0]), "r"(a[1]), "r"(a[2]), "r"(a[3]), "r"(b0), "r"(b1));
}

// ---------------- weight combo prep (+ w1 transpose) ----------------
__global__ void wprep_kernel(const float* __restrict__ w1,
                             const float* __restrict__ w2,
                             const float* __restrict__ w3) {
    const size_t S2 = (size_t)HID * HID;
    const size_t S3 = (size_t)OUTD * HID;
    const size_t S1 = (size_t)4 * HID * 7;
    const size_t stride = (size_t)gridDim.x * blockDim.x;
    // w1 transpose: [d][i][j] -> [d][j][i]  (coalesced reads for layer1)
    for (size_t n = (size_t)blockIdx.x * blockDim.x + threadIdx.x; n < S1; n += stride) {
        const int j = (int)(n % 7);
        const size_t di = n / 7;          // d*HID + i
        const int d = (int)(di / HID);
        const int i = (int)(di % HID);
        g_w1t[((size_t)d * 7 + j) * HID + i] = w1[n];
    }
    for (size_t i = (size_t)blockIdx.x * blockDim.x + threadIdx.x; i < S2; i += stride) {
        float a = w2[i], b = w2[S2 + i], c = w2[2 * S2 + i], d = w2[3 * S2 + i];
        g_w2h[0 * S2 + i] = __float2half(a + b + c + d);
        g_w2h[1 * S2 + i] = __float2half(a - b + c - d);
        g_w2h[2 * S2 + i] = __float2half(a - c);
        g_w2h[3 * S2 + i] = __float2half(-a + b + c - d);
        g_w2h[4 * S2 + i] = __float2half(a + b - c - d);
    }
    for (size_t i = (size_t)blockIdx.x * blockDim.x + threadIdx.x; i < S3; i += stride) {
        float a = w3[i], b = w3[S3 + i], c = w3[2 * S3 + i], d = w3[3 * S3 + i];
        g_w3h[0 * S3 + i] = __float2half(a + b + c + d);
        g_w3h[1 * S3 + i] = __float2half(a - b + c - d);
        g_w3h[2 * S3 + i] = __float2half(a - c);
        g_w3h[3 * S3 + i] = __float2half(-a + b + c - d);
        g_w3h[4 * S3 + i] = __float2half(a + b - c - d);
    }
}

// ---------------- layer 1: 16 rows per CTA, coalesced w1t reads ----------------
__global__ void layer1_kernel(const float* __restrict__ ins,
                              const float* __restrict__ b1) {
    __shared__ float patch[16][25];
    __shared__ float feat[16][4][7];
    const int row0 = blockIdx.x * 16;
    const int t = threadIdx.x;

    for (int idx = t; idx < 400; idx += 256)
        patch[idx / 25][idx % 25] = ins[(size_t)row0 * 25 + idx];
    __syncthreads();
    for (int idx = t; idx < 448; idx += 256) {
        const int r = idx / 28, k = idx % 28;
        feat[r][k / 7][k % 7] = patch[r][c_orbit[k]];
    }
    __syncthreads();

    for (int i = t; i < HID; i += 256) {
        const float bv = b1[i];
        float w[4][7];
        #pragma unroll
        for (int d = 0; d < 4; d++)
            #pragma unroll
            for (int j = 0; j < 7; j++)
                w[d][j] = g_w1t[((size_t)d * 7 + j) * HID + i];   // unit-stride across threads

        for (int r = 0; r < 16; r++) {
            float acc[4] = {bv, bv, bv, bv};
            #pragma unroll
            for (int d = 0; d < 4; d++) {
                #pragma unroll
                for (int g = 0; g < 4; g++) {
                    const float* f = feat[r][(g + d) & 3];
                    float a = 0.f;
                    #pragma unroll
                    for (int j = 0; j < 7; j++) a += w[d][j] * f[j];
                    acc[g] += a;
                }
            }
            const float r0 = fmaxf(acc[0], 0.f), r1 = fmaxf(acc[1], 0.f);
            const float r2 = fmaxf(acc[2], 0.f), r3 = fmaxf(acc[3], 0.f);
            const float xr = r0 - r2, xi = r3 - r1;
            const size_t off = (size_t)(row0 + r) * HID + i;
            g_act1[0 * PLANE + off] = __float2half(r0 + r1 + r2 + r3);
            g_act1[1 * PLANE + off] = __float2half(r0 - r1 + r2 - r3);
            g_act1[2 * PLANE + off] = __float2half(xr + xi);
            g_act1[3 * PLANE + off] = __float2half(xr);
            g_act1[4 * PLANE + off] = __float2half(xi);
        }
    }
}

// ---------------- batched GEMM: C[j] = A[j] @ B[j]^T  (j = 0..4) ----------------
// R13-exact (frozen): R6 schedule + R10 fragment double buffering + R11
// coalesced smem-staged epilogue, fp16 output both layers.
static constexpr int GEMM_SMEM = 3 * 16384 * 2;  // 98304

template <int LAYER>
__global__ __launch_bounds__(256, 2)
void gemm_kernel() {
    constexpr int BK = 64;
    constexpr int KT = HID / BK;  // 32
    constexpr size_t BSTRIDE = (LAYER == 2) ? (size_t)HID * HID : (size_t)OUTD * HID;
    constexpr int CP = (LAYER == 2) ? HID : OUTD;

    extern __shared__ char smem[];
    const uint32_t sA = smem_u32(smem);            // [3][16KB]
    const uint32_t sB = sA + 3 * 16384;            // [3][16KB]

    const int tid = threadIdx.x;
    const int j = blockIdx.z;
    const int brow = blockIdx.y * 128;
    const int bcol = blockIdx.x * 128;

    const __half* Aall = (LAYER == 2) ? g_act1 : g_act2;
    const __half* Ball = (LAYER == 2) ? g_w2h : g_w3h;
    const char* Ag = (const char*)(Aall + (size_t)j * PLANE + (size_t)brow * HID);
    const char* Bg = (const char*)(Ball + (size_t)j * BSTRIDE + (size_t)bcol * HID);

    // loader mapping: thread t -> 16B group lg of rows lr0 + 32*i
    const int lg = tid & 7;
    const int lr0 = tid >> 3;

    auto issue = [&](int st, int kt) {
        const uint32_t dA = sA + st * 16384, dB = sB + st * 16384;
        const char* gA = Ag + (size_t)kt * 128;
        const char* gB = Bg + (size_t)kt * 128;
        #pragma unroll
        for (int i = 0; i < 4; i++) {
            const int r = lr0 + i * 32;
            const uint32_t ph = (uint32_t)r * 128 + (uint32_t)((lg ^ (r & 7)) * 16);
            cp16(dA + ph, gA + (size_t)r * (HID * 2) + lg * 16);
            cp16(dB + ph, gB + (size_t)r * (HID * 2) + lg * 16);
        }
        asm volatile("cp.async.commit_group;\n");
    };

    issue(0, 0);
    issue(1, 1);

    const int warp = tid >> 5, lane = tid & 31;
    const int wm = (warp >> 2) * 64;   // 2 warp rows
    const int wn = (warp & 3) * 32;    // 4 warp cols
    const int rl = (lane & 7) + (((lane >> 3) & 1) << 3);  // 0..15
    const int hs = (lane >> 4) & 1;
    const int sw = lane & 7;

    float acc[4][4][4];
    #pragma unroll
    for (int m = 0; m < 4; m++)
        #pragma unroll
        for (int n = 0; n < 4; n++)
            #pragma unroll
            for (int q = 0; q < 4; q++) acc[m][n][q] = 0.f;

    for (int kt = 0; kt < KT; kt++) {
        asm volatile("cp.async.wait_group 1;\n");
        __syncthreads();   // fences prev-iter readers of stage (kt+2)%3

        const int st = kt % 3;
        const uint32_t aBase = sA + st * 16384 + (uint32_t)(wm + rl) * 128;
        const uint32_t bBase = sB + st * 16384 + (uint32_t)(wn + rl) * 128;

        // double-buffered fragments across kk
        uint32_t af[2][4][4], bf[2][2][4];

        // preload kk = 0
        {
            const uint32_t goff = (uint32_t)((hs ^ sw) * 16);
            #pragma unroll
            for (int n2 = 0; n2 < 2; n2++)
                LDSM4(bf[0][n2][0], bf[0][n2][1], bf[0][n2][2], bf[0][n2][3],
                      bBase + n2 * 16 * 128 + goff);
            #pragma unroll
            for (int m = 0; m < 4; m++)
                LDSM4(af[0][m][0], af[0][m][1], af[0][m][2], af[0][m][3],
                      aBase + m * 16 * 128 + goff);
        }

        #pragma unroll
        for (int kk = 0; kk < 4; kk++) {
            const int cur = kk & 1, nxt = cur ^ 1;
            // prefetch kk+1 fragments BEFORE this kk's MMAs
            if (kk < 3) {
                const uint32_t goff = (uint32_t)((((kk + 1) * 2 + hs) ^ sw) * 16);
                #pragma unroll
                for (int n2 = 0; n2 < 2; n2++)
                    LDSM4(bf[nxt][n2][0], bf[nxt][n2][1], bf[nxt][n2][2], bf[nxt][n2][3],
                          bBase + n2 * 16 * 128 + goff);
                #pragma unroll
                for (int m = 0; m < 4; m++)
                    LDSM4(af[nxt][m][0], af[nxt][m][1], af[nxt][m][2], af[nxt][m][3],
                          aBase + m * 16 * 128 + goff);
            }
            #pragma unroll
            for (int m = 0; m < 4; m++) {
                #pragma unroll
                for (int n2 = 0; n2 < 2; n2++) {
                    mma16816(acc[m][n2 * 2 + 0], af[cur][m], bf[cur][n2][0], bf[cur][n2][2]);
                    mma16816(acc[m][n2 * 2 + 1], af[cur][m], bf[cur][n2][1], bf[cur][n2][3]);
                }
            }
            // combined issue+commit right after first kk block (R6-proven placement)
            if (kk == 0) {
                if (kt + 2 < KT) issue((kt + 2) % 3, kt + 2);
                else asm volatile("cp.async.commit_group;\n");
            }
        }
    }

    // ---- epilogue: stage C (fp16) through smem, then coalesced 16-B stores ----
    asm volatile("cp.async.wait_group 0;\n");   // drain tail copies into stage slots
    __syncthreads();                             // all warps done with mainloop smem

    const int r0 = lane >> 2, cql = (lane & 3) * 2;
    constexpr int PT = 136;                      // halves; 16B-aligned rows, +4 bank shift/row
    __half* sC = (__half*)smem;
    #pragma unroll
    for (int m = 0; m < 4; m++) {
        #pragma unroll
        for (int jn = 0; jn < 4; jn++) {
            const int rr = wm + m * 16 + r0;
            const int cc = wn + (jn >> 1) * 16 + (jn & 1) * 8 + cql;
            *(__half2*)&sC[(size_t)rr * PT + cc] =
                __floats2half2_rn(acc[m][jn][0], acc[m][jn][1]);
            *(__half2*)&sC[(size_t)(rr + 8) * PT + cc] =
                __floats2half2_rn(acc[m][jn][2], acc[m][jn][3]);
        }
    }
    __syncthreads();
    __half* C = (LAYER == 2) ? (g_pre2 + (size_t)j * PLANE)
                             : (g_out3h + (size_t)j * OPLANE);
    #pragma unroll
    for (int i = 0; i < 8; i++) {                // 2048 chunks of 16B / 256 thr
        const int idx = tid + i * 256;
        const int rr = idx >> 4;
        const int cc = (idx & 15) * 8;
        uint4 v = *(const uint4*)&sC[(size_t)rr * PT + cc];
        *(uint4*)&C[(size_t)(brow + rr) * CP + bcol + cc] = v;
    }
}

// ---------------- inverse DFT + bias + LN + relu + forward DFT ----------------
__global__ void ln_tf_kernel(const float* __restrict__ b2,
                             const float* __restrict__ lng,
                             const float* __restrict__ lnb) {
    const size_t rf = blockIdx.x;
    const int t = threadIdx.x;
    const size_t off = rf * HID;
    const int c0 = t * 8;

    float P[5][8];
    #pragma unroll
    for (int jp = 0; jp < 5; jp++) {
        float4 v = *((const float4*)(g_pre2 + jp * PLANE + off) + t);
        const __half2* h = (const __half2*)&v;
        #pragma unroll
        for (int k = 0; k < 4; k++) {
            float2 f = __half22float2(h[k]);
            P[jp][2 * k] = f.x;
            P[jp][2 * k + 1] = f.y;
        }
    }

    float bb[8];
    *(float4*)&bb[0] = *(const float4*)&b2[c0];
    *(float4*)&bb[4] = *(const float4*)&b2[c0 + 4];

    float y[4][8];
    float s[4] = {0.f, 0.f, 0.f, 0.f}, q[4] = {0.f, 0.f, 0.f, 0.f};
    #pragma unroll
    for (int k = 0; k < 8; k++) {
        const float yr = P[2][k] - P[4][k];
        const float yi = P[2][k] + P[3][k];
        const float e = P[0][k] + P[1][k], o = P[0][k] - P[1][k];
        y[0][k] = 0.25f * (e + 2.f * yr) + bb[k];
        y[1][k] = 0.25f * (o - 2.f * yi) + bb[k];
        y[2][k] = 0.25f * (e - 2.f * yr) + bb[k];
        y[3][k] = 0.25f * (o + 2.f * yi) + bb[k];
        #pragma unroll
        for (int g = 0; g < 4; g++) { s[g] += y[g][k]; q[g] += y[g][k] * y[g][k]; }
    }

    __shared__ float ss[4][8], qq[4][8];
    const int warp = t >> 5, lane = t & 31;
    #pragma unroll
    for (int g = 0; g < 4; g++) {
        #pragma unroll
        for (int o = 16; o > 0; o >>= 1) {
            s[g] += __shfl_down_sync(0xffffffffu, s[g], o);
            q[g] += __shfl_down_sync(0xffffffffu, q[g], o);
        }
        if (lane == 0) { ss[g][warp] = s[g]; qq[g][warp] = q[g]; }
    }
    __syncthreads();
    __shared__ float mean[4], rstd[4];
    if (t < 4) {
        float a = 0.f, b = 0.f;
        #pragma unroll
        for (int w = 0; w < 8; w++) { a += ss[t][w]; b += qq[t][w]; }
        const float m = a * (1.f / HID);
        mean[t] = m;
        rstd[t] = rsqrtf(b * (1.f / HID) - m * m + 1e-5f);
    }
    __syncthreads();

    float gv[8], bv[8];
    *(float4*)&gv[0] = *(const float4*)&lng[c0];
    *(float4*)&gv[4] = *(const float4*)&lng[c0 + 4];
    *(float4*)&bv[0] = *(const float4*)&lnb[c0];
    *(float4*)&bv[4] = *(const float4*)&lnb[c0 + 4];

    float r[4][8];
    #pragma unroll
    for (int k = 0; k < 8; k++) {
        #pragma unroll
        for (int g = 0; g < 4; g++)
            r[g][k] = fmaxf((y[g][k] - mean[g]) * rstd[g] * gv[k] + bv[k], 0.f);
    }

    float Z[5][8];
    #pragma unroll
    for (int k = 0; k < 8; k++) {
        const float zr = r[0][k] - r[2][k], zi = r[3][k] - r[1][k];
        Z[0][k] = r[0][k] + r[1][k] + r[2][k] + r[3][k];
        Z[1][k] = r[0][k] - r[1][k] + r[2][k] - r[3][k];
        Z[2][k] = zr + zi;
        Z[3][k] = zr;
        Z[4][k] = zi;
    }
    #pragma unroll
    for (int jp = 0; jp < 5; jp++) {
        float4 v;
        __half2* h = (__half2*)&v;
        #pragma unroll
        for (int k = 0; k < 4; k++)
            h[k] = __floats2half2_rn(Z[jp][2 * k], Z[jp][2 * k + 1]);
        *((float4*)(g_act2 + jp * PLANE + off) + t) = v;
    }
}

// ---------------- final: inverse DFT + bias b3 -> out ----------------
__global__ void combine3_kernel(const float* __restrict__ b3, float* __restrict__ out) {
    const size_t row = blockIdx.x;
    const int t = threadIdx.x;
    const int g = t >> 6;
    const int c0 = (t & 63) * 8;
    const size_t poff = row * OUTD + c0;

    float P[5][8];
    #pragma unroll
    for (int jp = 0; jp < 5; jp++) {
        uint4 v = *(const uint4*)(g_out3h + (size_t)jp * OPLANE + poff);
        const __half2* h = (const __half2*)&v;
        #pragma unroll
        for (int k = 0; k < 4; k++) {
            float2 f = __half22float2(h[k]);
            P[jp][2 * k] = f.x;
            P[jp][2 * k + 1] = f.y;
        }
    }
    float o[8];
    #pragma unroll
    for (int k = 0; k < 8; k++) {
        const float yr = P[2][k] - P[4][k];
        const float yi = P[2][k] + P[3][k];
        const float e = P[0][k] + P[1][k], od = P[0][k] - P[1][k];
        float v;
        if (g == 0)      v = 0.25f * (e + 2.f * yr);
        else if (g == 1) v = 0.25f * (od - 2.f * yi);
        else if (g == 2) v = 0.25f * (e - 2.f * yr);
        else             v = 0.25f * (od + 2.f * yi);
        o[k] = v + __ldg(&b3[c0 + k]);
    }
    float* dst = out + row * 2048 + (size_t)g * OUTD + c0;
    *(float4*)&dst[0] = *(const float4*)&o[0];
    *(float4*)&dst[4] = *(const float4*)&o[4];
}

// ---------------- launch ----------------
extern "C" void kernel_launch(void* const* d_in, const int* in_sizes, int n_in,
                              void* d_out, int out_size) {
    const float* ins = (const float*)d_in[0];
    const float* w1 = (const float*)d_in[1];
    const float* b1 = (const float*)d_in[2];
    const float* w2 = (const float*)d_in[3];
    const float* b2 = (const float*)d_in[4];
    const float* w3 = (const float*)d_in[5];
    const float* b3 = (const float*)d_in[6];
    const float* lng = (const float*)d_in[7];
    const float* lnb = (const float*)d_in[8];
    float* out = (float*)d_out;

    cudaFuncSetAttribute(gemm_kernel<2>, cudaFuncAttributeMaxDynamicSharedMemorySize, GEMM_SMEM);
    cudaFuncSetAttribute(gemm_kernel<3>, cudaFuncAttributeMaxDynamicSharedMemorySize, GEMM_SMEM);

    wprep_kernel<<<2048, 256>>>(w1, w2, w3);
    layer1_kernel<<<BROWS / 16, 256>>>(ins, b1);

    {
        dim3 grid(HID / 128, BROWS / 128, 5);   // (16, 80, 5)
        gemm_kernel<2><<<grid, 256, GEMM_SMEM>>>();
    }
    ln_tf_kernel<<<BROWS, 256>>>(b2, lng, lnb);
    {
        dim3 grid(OUTD / 128, BROWS / 128, 5);  // (4, 80, 5)
        gemm_kernel<3><<<grid, 256, GEMM_SMEM>>>();
    }
    combine3_kernel<<<BROWS, 256>>>(b3, out);
}

// round 16
// speedup vs baseline: 1.0426x; 1.0194x over previous
#include <cuda_runtime.h>
#include <cuda_fp16.h>
#include <cstdint>

// ---------------- problem constants ----------------
#define BROWS 10240          // B*N = 2048*5
#define HID   2048
#define OUTD  512
#define PLANE ((size_t)BROWS * HID)
#define OPLANE ((size_t)BROWS * OUTD)

// ---------------- persistent device scratch ----------------
// 5 DFT planes: [0]=X0, [1]=X2, [2]=Xs(=Xr+Xi), [3]=Xr, [4]=Xi
__device__ __align__(1024) __half g_act1[5 * PLANE];
__device__ __align__(1024) __half g_pre2[5 * PLANE];
__device__ __align__(1024) __half g_act2[5 * PLANE];
__device__ __align__(1024) __half g_w2h[(size_t)5 * HID * HID];
__device__ __align__(1024) __half g_w3h[(size_t)5 * OUTD * HID];
__device__ __align__(1024) __half g_out3h[5 * OPLANE];   // layer3 GEMM out (fp16)
__device__ __align__(1024) float  g_w1c[5 * 7 * HID];    // w1 DFT combos [p][j][i]

// ---------------- orbit table ----------------
__constant__ int c_orbit[28] = {
    12, 0, 1, 2, 5, 6, 7,
    12, 4, 9, 14, 3, 8, 13,
    12, 24, 23, 22, 19, 18, 17,
    12, 20, 15, 10, 21, 16, 11
};

// ---------------- PTX helpers (baseline PTX only) ----------------
__device__ __forceinline__ uint32_t smem_u32(const void* p) {
    uint32_t a;
    asm("{ .reg .u64 t; cvta.to.shared.u64 t, %1; cvt.u32.u64 %0, t; }" : "=r"(a) : "l"(p));
    return a;
}
__device__ __forceinline__ void cp16(uint32_t d, const void* g) {
    asm volatile("cp.async.cg.shared.global [%0],[%1],16;\n" ::"r"(d), "l"(g));
}
#define LDSM4(r0, r1, r2, r3, addr) \
    asm volatile("ldmatrix.sync.aligned.m8n8.x4.shared.b16 {%0,%1,%2,%3},[%4];" \
                 : "=r"(r0), "=r"(r1), "=r"(r2), "=r"(r3) : "r"(addr))

__device__ __forceinline__ void mma16816(float* c, const uint32_t* a, uint32_t b0, uint32_t b1) {
    asm volatile(
        "mma.sync.aligned.m16n8k16.row.col.f32.f16.f16.f32 "
        "{%0,%1,%2,%3},{%4,%5,%6,%7},{%8,%9},{%0,%1,%2,%3};"
        : "+f"(c[0]), "+f"(c[1]), "+f"(c[2]), "+f"(c[3])
        : "r"(a[0]), "r"(a[1]), "r"(a[2]), "r"(a[3]), "r"(b0), "r"(b1));
}

// ---------------- weight combo prep (w1/w2/w3 DFT combos) ----------------
__global__ void wprep_kernel(const float* __restrict__ w1,
                             const float* __restrict__ w2,
                             const float* __restrict__ w3) {
    const size_t S2 = (size_t)HID * HID;
    const size_t S3 = (size_t)OUTD * HID;
    const size_t S1 = (size_t)HID * 7;
    const size_t stride = (size_t)gridDim.x * blockDim.x;
    // w1 combos: [d][i][j] -> [p][j][i]  (coalesced over i for layer1)
    for (size_t n = (size_t)blockIdx.x * blockDim.x + threadIdx.x; n < S1; n += stride) {
        const int i = (int)(n / 7);
        const int j = (int)(n % 7);
        const float a = w1[((size_t)0 * HID + i) * 7 + j];
        const float b = w1[((size_t)1 * HID + i) * 7 + j];
        const float c = w1[((size_t)2 * HID + i) * 7 + j];
        const float d = w1[((size_t)3 * HID + i) * 7 + j];
        g_w1c[(0 * 7 + j) * HID + i] = a + b + c + d;
        g_w1c[(1 * 7 + j) * HID + i] = a - b + c - d;
        g_w1c[(2 * 7 + j) * HID + i] = a - c;
        g_w1c[(3 * 7 + j) * HID + i] = -a + b + c - d;
        g_w1c[(4 * 7 + j) * HID + i] = a + b - c - d;
    }
    for (size_t i = (size_t)blockIdx.x * blockDim.x + threadIdx.x; i < S2; i += stride) {
        float a = w2[i], b = w2[S2 + i], c = w2[2 * S2 + i], d = w2[3 * S2 + i];
        g_w2h[0 * S2 + i] = __float2half(a + b + c + d);
        g_w2h[1 * S2 + i] = __float2half(a - b + c - d);
        g_w2h[2 * S2 + i] = __float2half(a - c);
        g_w2h[3 * S2 + i] = __float2half(-a + b + c - d);
        g_w2h[4 * S2 + i] = __float2half(a + b - c - d);
    }
    for (size_t i = (size_t)blockIdx.x * blockDim.x + threadIdx.x; i < S3; i += stride) {
        float a = w3[i], b = w3[S3 + i], c = w3[2 * S3 + i], d = w3[3 * S3 + i];
        g_w3h[0 * S3 + i] = __float2half(a + b + c + d);
        g_w3h[1 * S3 + i] = __float2half(a - b + c - d);
        g_w3h[2 * S3 + i] = __float2half(a - c);
        g_w3h[3 * S3 + i] = __float2half(-a + b + c - d);
        g_w3h[4 * S3 + i] = __float2half(a + b - c - d);
    }
}

// ---------------- layer 1: DFT-decomposed c4conv (5 length-7 dots vs 16) ----------------
__global__ void layer1_kernel(const float* __restrict__ ins,
                              const float* __restrict__ b1) {
    __shared__ float patch[16][25];
    __shared__ float feat[16][4][7];
    __shared__ float fp[16][5][7];    // input DFT planes per row
    const int row0 = blockIdx.x * 16;
    const int t = threadIdx.x;

    for (int idx = t; idx < 400; idx += 256)
        patch[idx / 25][idx % 25] = ins[(size_t)row0 * 25 + idx];
    __syncthreads();
    for (int idx = t; idx < 448; idx += 256) {
        const int r = idx / 28, k = idx % 28;
        feat[r][k / 7][k % 7] = patch[r][c_orbit[k]];
    }
    __syncthreads();
    for (int idx = t; idx < 112; idx += 256) {   // 16 rows x 7 features
        const int r = idx / 7, jf = idx % 7;
        const float f0 = feat[r][0][jf], f1 = feat[r][1][jf];
        const float f2 = feat[r][2][jf], f3 = feat[r][3][jf];
        const float xr = f0 - f2, xi = f3 - f1;
        fp[r][0][jf] = f0 + f1 + f2 + f3;
        fp[r][1][jf] = f0 - f1 + f2 - f3;
        fp[r][2][jf] = xr + xi;
        fp[r][3][jf] = xr;
        fp[r][4][jf] = xi;
    }
    __syncthreads();

    for (int i = t; i < HID; i += 256) {
        const float bv = b1[i];
        float w[5][7];
        #pragma unroll
        for (int p = 0; p < 5; p++)
            #pragma unroll
            for (int jf = 0; jf < 7; jf++)
                w[p][jf] = g_w1c[((size_t)p * 7 + jf) * HID + i];   // unit-stride

        for (int r = 0; r < 16; r++) {
            float P[5] = {0.f, 0.f, 0.f, 0.f, 0.f};
            #pragma unroll
            for (int p = 0; p < 5; p++) {
                #pragma unroll
                for (int jf = 0; jf < 7; jf++)
                    P[p] += w[p][jf] * fp[r][p][jf];
            }
            const float yr = P[2] - P[4];
            const float yi = P[2] + P[3];
            const float e = P[0] + P[1], o = P[0] - P[1];
            const float y0 = 0.25f * (e + 2.f * yr) + bv;
            const float y1 = 0.25f * (o - 2.f * yi) + bv;
            const float y2 = 0.25f * (e - 2.f * yr) + bv;
            const float y3 = 0.25f * (o + 2.f * yi) + bv;
            const float r0 = fmaxf(y0, 0.f), r1 = fmaxf(y1, 0.f);
            const float r2 = fmaxf(y2, 0.f), r3 = fmaxf(y3, 0.f);
            const float zr = r0 - r2, zi = r3 - r1;
            const size_t off = (size_t)(row0 + r) * HID + i;
            g_act1[0 * PLANE + off] = __float2half(r0 + r1 + r2 + r3);
            g_act1[1 * PLANE + off] = __float2half(r0 - r1 + r2 - r3);
            g_act1[2 * PLANE + off] = __float2half(zr + zi);
            g_act1[3 * PLANE + off] = __float2half(zr);
            g_act1[4 * PLANE + off] = __float2half(zi);
        }
    }
}

// ---------------- batched GEMM: C[j] = A[j] @ B[j]^T  (j = 0..4) ----------------
// R13-exact (frozen): R6 schedule + R10 fragment double buffering + R11
// coalesced smem-staged epilogue, fp16 output both layers.
static constexpr int GEMM_SMEM = 3 * 16384 * 2;  // 98304

template <int LAYER>
__global__ __launch_bounds__(256, 2)
void gemm_kernel() {
    constexpr int BK = 64;
    constexpr int KT = HID / BK;  // 32
    constexpr size_t BSTRIDE = (LAYER == 2) ? (size_t)HID * HID : (size_t)OUTD * HID;
    constexpr int CP = (LAYER == 2) ? HID : OUTD;

    extern __shared__ char smem[];
    const uint32_t sA = smem_u32(smem);            // [3][16KB]
    const uint32_t sB = sA + 3 * 16384;            // [3][16KB]

    const int tid = threadIdx.x;
    const int j = blockIdx.z;
    const int brow = blockIdx.y * 128;
    const int bcol = blockIdx.x * 128;

    const __half* Aall = (LAYER == 2) ? g_act1 : g_act2;
    const __half* Ball = (LAYER == 2) ? g_w2h : g_w3h;
    const char* Ag = (const char*)(Aall + (size_t)j * PLANE + (size_t)brow * HID);
    const char* Bg = (const char*)(Ball + (size_t)j * BSTRIDE + (size_t)bcol * HID);

    // loader mapping: thread t -> 16B group lg of rows lr0 + 32*i
    const int lg = tid & 7;
    const int lr0 = tid >> 3;

    auto issue = [&](int st, int kt) {
        const uint32_t dA = sA + st * 16384, dB = sB + st * 16384;
        const char* gA = Ag + (size_t)kt * 128;
        const char* gB = Bg + (size_t)kt * 128;
        #pragma unroll
        for (int i = 0; i < 4; i++) {
            const int r = lr0 + i * 32;
            const uint32_t ph = (uint32_t)r * 128 + (uint32_t)((lg ^ (r & 7)) * 16);
            cp16(dA + ph, gA + (size_t)r * (HID * 2) + lg * 16);
            cp16(dB + ph, gB + (size_t)r * (HID * 2) + lg * 16);
        }
        asm volatile("cp.async.commit_group;\n");
    };

    issue(0, 0);
    issue(1, 1);

    const int warp = tid >> 5, lane = tid & 31;
    const int wm = (warp >> 2) * 64;   // 2 warp rows
    const int wn = (warp & 3) * 32;    // 4 warp cols
    const int rl = (lane & 7) + (((lane >> 3) & 1) << 3);  // 0..15
    const int hs = (lane >> 4) & 1;
    const int sw = lane & 7;

    float acc[4][4][4];
    #pragma unroll
    for (int m = 0; m < 4; m++)
        #pragma unroll
        for (int n = 0; n < 4; n++)
            #pragma unroll
            for (int q = 0; q < 4; q++) acc[m][n][q] = 0.f;

    for (int kt = 0; kt < KT; kt++) {
        asm volatile("cp.async.wait_group 1;\n");
        __syncthreads();   // fences prev-iter readers of stage (kt+2)%3

        const int st = kt % 3;
        const uint32_t aBase = sA + st * 16384 + (uint32_t)(wm + rl) * 128;
        const uint32_t bBase = sB + st * 16384 + (uint32_t)(wn + rl) * 128;

        // double-buffered fragments across kk
        uint32_t af[2][4][4], bf[2][2][4];

        // preload kk = 0
        {
            const uint32_t goff = (uint32_t)((hs ^ sw) * 16);
            #pragma unroll
            for (int n2 = 0; n2 < 2; n2++)
                LDSM4(bf[0][n2][0], bf[0][n2][1], bf[0][n2][2], bf[0][n2][3],
                      bBase + n2 * 16 * 128 + goff);
            #pragma unroll
            for (int m = 0; m < 4; m++)
                LDSM4(af[0][m][0], af[0][m][1], af[0][m][2], af[0][m][3],
                      aBase + m * 16 * 128 + goff);
        }

        #pragma unroll
        for (int kk = 0; kk < 4; kk++) {
            const int cur = kk & 1, nxt = cur ^ 1;
            // prefetch kk+1 fragments BEFORE this kk's MMAs
            if (kk < 3) {
                const uint32_t goff = (uint32_t)((((kk + 1) * 2 + hs) ^ sw) * 16);
                #pragma unroll
                for (int n2 = 0; n2 < 2; n2++)
                    LDSM4(bf[nxt][n2][0], bf[nxt][n2][1], bf[nxt][n2][2], bf[nxt][n2][3],
                          bBase + n2 * 16 * 128 + goff);
                #pragma unroll
                for (int m = 0; m < 4; m++)
                    LDSM4(af[nxt][m][0], af[nxt][m][1], af[nxt][m][2], af[nxt][m][3],
                          aBase + m * 16 * 128 + goff);
            }
            #pragma unroll
            for (int m = 0; m < 4; m++) {
                #pragma unroll
                for (int n2 = 0; n2 < 2; n2++) {
                    mma16816(acc[m][n2 * 2 + 0], af[cur][m], bf[cur][n2][0], bf[cur][n2][2]);
                    mma16816(acc[m][n2 * 2 + 1], af[cur][m], bf[cur][n2][1], bf[cur][n2][3]);
                }
            }
            // combined issue+commit right after first kk block (R6-proven placement)
            if (kk == 0) {
                if (kt + 2 < KT) issue((kt + 2) % 3, kt + 2);
                else asm volatile("cp.async.commit_group;\n");
            }
        }
    }

    // ---- epilogue: stage C (fp16) through smem, then coalesced 16-B stores ----
    asm volatile("cp.async.wait_group 0;\n");   // drain tail copies into stage slots
    __syncthreads();                             // all warps done with mainloop smem

    const int r0 = lane >> 2, cql = (lane & 3) * 2;
    constexpr int PT = 136;                      // halves; 16B-aligned rows, +4 bank shift/row
    __half* sC = (__half*)smem;
    #pragma unroll
    for (int m = 0; m < 4; m++) {
        #pragma unroll
        for (int jn = 0; jn < 4; jn++) {
            const int rr = wm + m * 16 + r0;
            const int cc = wn + (jn >> 1) * 16 + (jn & 1) * 8 + cql;
            *(__half2*)&sC[(size_t)rr * PT + cc] =
                __floats2half2_rn(acc[m][jn][0], acc[m][jn][1]);
            *(__half2*)&sC[(size_t)(rr + 8) * PT + cc] =
                __floats2half2_rn(acc[m][jn][2], acc[m][jn][3]);
        }
    }
    __syncthreads();
    __half* C = (LAYER == 2) ? (g_pre2 + (size_t)j * PLANE)
                             : (g_out3h + (size_t)j * OPLANE);
    #pragma unroll
    for (int i = 0; i < 8; i++) {                // 2048 chunks of 16B / 256 thr
        const int idx = tid + i * 256;
        const int rr = idx >> 4;
        const int cc = (idx & 15) * 8;
        uint4 v = *(const uint4*)&sC[(size_t)rr * PT + cc];
        *(uint4*)&C[(size_t)(brow + rr) * CP + bcol + cc] = v;
    }
}

// ---------------- inverse DFT + bias + LN + relu + forward DFT ----------------
__global__ void ln_tf_kernel(const float* __restrict__ b2,
                             const float* __restrict__ lng,
                             const float* __restrict__ lnb) {
    const size_t rf = blockIdx.x;
    const int t = threadIdx.x;
    const size_t off = rf * HID;
    const int c0 = t * 8;

    float P[5][8];
    #pragma unroll
    for (int jp = 0; jp < 5; jp++) {
        float4 v = *((const float4*)(g_pre2 + jp * PLANE + off) + t);
        const __half2* h = (const __half2*)&v;
        #pragma unroll
        for (int k = 0; k < 4; k++) {
            float2 f = __half22float2(h[k]);
            P[jp][2 * k] = f.x;
            P[jp][2 * k + 1] = f.y;
        }
    }

    float bb[8];
    *(float4*)&bb[0] = *(const float4*)&b2[c0];
    *(float4*)&bb[4] = *(const float4*)&b2[c0 + 4];

    float y[4][8];
    float s[4] = {0.f, 0.f, 0.f, 0.f}, q[4] = {0.f, 0.f, 0.f, 0.f};
    #pragma unroll
    for (int k = 0; k < 8; k++) {
        const float yr = P[2][k] - P[4][k];
        const float yi = P[2][k] + P[3][k];
        const float e = P[0][k] + P[1][k], o = P[0][k] - P[1][k];
        y[0][k] = 0.25f * (e + 2.f * yr) + bb[k];
        y[1][k] = 0.25f * (o - 2.f * yi) + bb[k];
        y[2][k] = 0.25f * (e - 2.f * yr) + bb[k];
        y[3][k] = 0.25f * (o + 2.f * yi) + bb[k];
        #pragma unroll
        for (int g = 0; g < 4; g++) { s[g] += y[g][k]; q[g] += y[g][k] * y[g][k]; }
    }

    __shared__ float ss[4][8], qq[4][8];
    const int warp = t >> 5, lane = t & 31;
    #pragma unroll
    for (int g = 0; g < 4; g++) {
        #pragma unroll
        for (int o = 16; o > 0; o >>= 1) {
            s[g] += __shfl_down_sync(0xffffffffu, s[g], o);
            q[g] += __shfl_down_sync(0xffffffffu, q[g], o);
        }
        if (lane == 0) { ss[g][warp] = s[g]; qq[g][warp] = q[g]; }
    }
    __syncthreads();
    __shared__ float mean[4], rstd[4];
    if (t < 4) {
        float a = 0.f, b = 0.f;
        #pragma unroll
        for (int w = 0; w < 8; w++) { a += ss[t][w]; b += qq[t][w]; }
        const float m = a * (1.f / HID);
        mean[t] = m;
        rstd[t] = rsqrtf(b * (1.f / HID) - m * m + 1e-5f);
    }
    __syncthreads();

    float gv[8], bv[8];
    *(float4*)&gv[0] = *(const float4*)&lng[c0];
    *(float4*)&gv[4] = *(const float4*)&lng[c0 + 4];
    *(float4*)&bv[0] = *(const float4*)&lnb[c0];
    *(float4*)&bv[4] = *(const float4*)&lnb[c0 + 4];

    float r[4][8];
    #pragma unroll
    for (int k = 0; k < 8; k++) {
        #pragma unroll
        for (int g = 0; g < 4; g++)
            r[g][k] = fmaxf((y[g][k] - mean[g]) * rstd[g] * gv[k] + bv[k], 0.f);
    }

    float Z[5][8];
    #pragma unroll
    for (int k = 0; k < 8; k++) {
        const float zr = r[0][k] - r[2][k], zi = r[3][k] - r[1][k];
        Z[0][k] = r[0][k] + r[1][k] + r[2][k] + r[3][k];
        Z[1][k] = r[0][k] - r[1][k] + r[2][k] - r[3][k];
        Z[2][k] = zr + zi;
        Z[3][k] = zr;
        Z[4][k] = zi;
    }
    #pragma unroll
    for (int jp = 0; jp < 5; jp++) {
        float4 v;
        __half2* h = (__half2*)&v;
        #pragma unroll
        for (int k = 0; k < 4; k++)
            h[k] = __floats2half2_rn(Z[jp][2 * k], Z[jp][2 * k + 1]);
        *((float4*)(g_act2 + jp * PLANE + off) + t) = v;
    }
}

// ---------------- final: inverse DFT + bias b3 -> out ----------------
__global__ void combine3_kernel(const float* __restrict__ b3, float* __restrict__ out) {
    const size_t row = blockIdx.x;
    const int t = threadIdx.x;
    const int g = t >> 6;
    const int c0 = (t & 63) * 8;
    const size_t poff = row * OUTD + c0;

    float P[5][8];
    #pragma unroll
    for (int jp = 0; jp < 5; jp++) {
        uint4 v = *(const uint4*)(g_out3h + (size_t)jp * OPLANE + poff);
        const __half2* h = (const __half2*)&v;
        #pragma unroll
        for (int k = 0; k < 4; k++) {
            float2 f = __half22float2(h[k]);
            P[jp][2 * k] = f.x;
            P[jp][2 * k + 1] = f.y;
        }
    }
    float o[8];
    #pragma unroll
    for (int k = 0; k < 8; k++) {
        const float yr = P[2][k] - P[4][k];
        const float yi = P[2][k] + P[3][k];
        const float e = P[0][k] + P[1][k], od = P[0][k] - P[1][k];
        float v;
        if (g == 0)      v = 0.25f * (e + 2.f * yr);
        else if (g == 1) v = 0.25f * (od - 2.f * yi);
        else if (g == 2) v = 0.25f * (e - 2.f * yr);
        else             v = 0.25f * (od + 2.f * yi);
        o[k] = v + __ldg(&b3[c0 + k]);
    }
    float* dst = out + row * 2048 + (size_t)g * OUTD + c0;
    *(float4*)&dst[0] = *(const float4*)&o[0];
    *(float4*)&dst[4] = *(const float4*)&o[4];
}

// ---------------- launch ----------------
extern "C" void kernel_launch(void* const* d_in, const int* in_sizes, int n_in,
                              void* d_out, int out_size) {
    const float* ins = (const float*)d_in[0];
    const float* w1 = (const float*)d_in[1];
    const float* b1 = (const float*)d_in[2];
    const float* w2 = (const float*)d_in[3];
    const float* b2 = (const float*)d_in[4];
    const float* w3 = (const float*)d_in[5];
    const float* b3 = (const float*)d_in[6];
    const float* lng = (const float*)d_in[7];
    const float* lnb = (const float*)d_in[8];
    float* out = (float*)d_out;

    cudaFuncSetAttribute(gemm_kernel<2>, cudaFuncAttributeMaxDynamicSharedMemorySize, GEMM_SMEM);
    cudaFuncSetAttribute(gemm_kernel<3>, cudaFuncAttributeMaxDynamicSharedMemorySize, GEMM_SMEM);

    wprep_kernel<<<2048, 256>>>(w1, w2, w3);
    layer1_kernel<<<BROWS / 16, 256>>>(ins, b1);

    {
        dim3 grid(HID / 128, BROWS / 128, 5);   // (16, 80, 5)
        gemm_kernel<2><<<grid, 256, GEMM_SMEM>>>();
    }
    ln_tf_kernel<<<BROWS, 256>>>(b2, lng, lnb);
    {
        dim3 grid(OUTD / 128, BROWS / 128, 5);  // (4, 80, 5)
        gemm_kernel<3><<<grid, 256, GEMM_SMEM>>>();
    }
    combine3_kernel<<<BROWS, 256>>>(b3, out);
}

// round 17
// speedup vs baseline: 1.0593x; 1.0160x over previous
#include <cuda_runtime.h>
#include <cuda_fp16.h>
#include <cstdint>

// ---------------- problem constants ----------------
#define BROWS 10240          // B*N = 2048*5
#define HID   2048
#define OUTD  512
#define PLANE ((size_t)BROWS * HID)
#define OPLANE ((size_t)BROWS * OUTD)

// ---------------- persistent device scratch ----------------
// 5 DFT planes: [0]=X0, [1]=X2, [2]=Xs(=Xr+Xi), [3]=Xr, [4]=Xi
__device__ __align__(1024) __half g_act1[5 * PLANE];
__device__ __align__(1024) __half g_pre2[5 * PLANE];
__device__ __align__(1024) __half g_act2[5 * PLANE];
__device__ __align__(1024) __half g_w2h[(size_t)5 * HID * HID];
__device__ __align__(1024) __half g_w3h[(size_t)5 * OUTD * HID];
__device__ __align__(1024) __half g_out3h[5 * OPLANE];   // layer3 GEMM out (fp16)
__device__ __align__(1024) float  g_w1c[5 * 7 * HID];    // w1 DFT combos [p][j][i]

// ---------------- orbit table ----------------
__constant__ int c_orbit[28] = {
    12, 0, 1, 2, 5, 6, 7,
    12, 4, 9, 14, 3, 8, 13,
    12, 24, 23, 22, 19, 18, 17,
    12, 20, 15, 10, 21, 16, 11
};

// ---------------- PTX helpers (baseline PTX only) ----------------
__device__ __forceinline__ uint32_t smem_u32(const void* p) {
    uint32_t a;
    asm("{ .reg .u64 t; cvta.to.shared.u64 t, %1; cvt.u32.u64 %0, t; }" : "=r"(a) : "l"(p));
    return a;
}
__device__ __forceinline__ void cp16(uint32_t d, const void* g) {
    asm volatile("cp.async.cg.shared.global [%0],[%1],16;\n" ::"r"(d), "l"(g));
}
#define LDSM4(r0, r1, r2, r3, addr) \
    asm volatile("ldmatrix.sync.aligned.m8n8.x4.shared.b16 {%0,%1,%2,%3},[%4];" \
                 : "=r"(r0), "=r"(r1), "=r"(r2), "=r"(r3) : "r"(addr))

__device__ __forceinline__ void mma16816(float* c, const uint32_t* a, uint32_t b0, uint32_t b1) {
    asm volatile(
        "mma.sync.aligned.m16n8k16.row.col.f32.f16.f16.f32 "
        "{%0,%1,%2,%3},{%4,%5,%6,%7},{%8,%9},{%0,%1,%2,%3};"
        : "+f"(c[0]), "+f"(c[1]), "+f"(c[2]), "+f"(c[3])
        : "r"(a[0]), "r"(a[1]), "r"(a[2]), "r"(a[3]), "r"(b0), "r"(b1));
}

// ---------------- fused prep: layer1 (blocks 0..639) + weight combos (640..2687) ----------------
#define L1_BLOCKS (BROWS / 16)     // 640
#define WP_BLOCKS 2048

__device__ void wprep_body(int bid,
                           const float* __restrict__ w1,
                           const float* __restrict__ w2,
                           const float* __restrict__ w3) {
    const size_t S2 = (size_t)HID * HID;
    const size_t S3 = (size_t)OUTD * HID;
    const size_t S1 = (size_t)HID * 7;
    const size_t stride = (size_t)WP_BLOCKS * 256;
    const size_t base = (size_t)bid * 256 + threadIdx.x;
    // w1 combos: [d][i][j] -> [p][j][i]
    for (size_t n = base; n < S1; n += stride) {
        const int i = (int)(n / 7);
        const int j = (int)(n % 7);
        const float a = w1[((size_t)0 * HID + i) * 7 + j];
        const float b = w1[((size_t)1 * HID + i) * 7 + j];
        const float c = w1[((size_t)2 * HID + i) * 7 + j];
        const float d = w1[((size_t)3 * HID + i) * 7 + j];
        g_w1c[(0 * 7 + j) * HID + i] = a + b + c + d;
        g_w1c[(1 * 7 + j) * HID + i] = a - b + c - d;
        g_w1c[(2 * 7 + j) * HID + i] = a - c;
        g_w1c[(3 * 7 + j) * HID + i] = -a + b + c - d;
        g_w1c[(4 * 7 + j) * HID + i] = a + b - c - d;
    }
    for (size_t i = base; i < S2; i += stride) {
        float a = w2[i], b = w2[S2 + i], c = w2[2 * S2 + i], d = w2[3 * S2 + i];
        g_w2h[0 * S2 + i] = __float2half(a + b + c + d);
        g_w2h[1 * S2 + i] = __float2half(a - b + c - d);
        g_w2h[2 * S2 + i] = __float2half(a - c);
        g_w2h[3 * S2 + i] = __float2half(-a + b + c - d);
        g_w2h[4 * S2 + i] = __float2half(a + b - c - d);
    }
    for (size_t i = base; i < S3; i += stride) {
        float a = w3[i], b = w3[S3 + i], c = w3[2 * S3 + i], d = w3[3 * S3 + i];
        g_w3h[0 * S3 + i] = __float2half(a + b + c + d);
        g_w3h[1 * S3 + i] = __float2half(a - b + c - d);
        g_w3h[2 * S3 + i] = __float2half(a - c);
        g_w3h[3 * S3 + i] = __float2half(-a + b + c - d);
        g_w3h[4 * S3 + i] = __float2half(a + b - c - d);
    }
}

// layer1 needs g_w1c, which the SAME kernel writes in other blocks -> layer1 must
// recompute its w combos directly from w1 (tiny: 35 floats per i) to stay
// dependency-free within the fused launch.
__device__ void layer1_body(int bid,
                            const float* __restrict__ ins,
                            const float* __restrict__ w1,
                            const float* __restrict__ b1) {
    __shared__ float patch[16][25];
    __shared__ float feat[16][4][7];
    __shared__ float fp[16][5][7];
    const int row0 = bid * 16;
    const int t = threadIdx.x;

    for (int idx = t; idx < 400; idx += 256)
        patch[idx / 25][idx % 25] = ins[(size_t)row0 * 25 + idx];
    __syncthreads();
    for (int idx = t; idx < 448; idx += 256) {
        const int r = idx / 28, k = idx % 28;
        feat[r][k / 7][k % 7] = patch[r][c_orbit[k]];
    }
    __syncthreads();
    for (int idx = t; idx < 112; idx += 256) {
        const int r = idx / 7, jf = idx % 7;
        const float f0 = feat[r][0][jf], f1 = feat[r][1][jf];
        const float f2 = feat[r][2][jf], f3 = feat[r][3][jf];
        const float xr = f0 - f2, xi = f3 - f1;
        fp[r][0][jf] = f0 + f1 + f2 + f3;
        fp[r][1][jf] = f0 - f1 + f2 - f3;
        fp[r][2][jf] = xr + xi;
        fp[r][3][jf] = xr;
        fp[r][4][jf] = xi;
    }
    __syncthreads();

    for (int i = t; i < HID; i += 256) {
        const float bv = b1[i];
        // compute the 5 w-combos for this i inline (28 loads, ~20 flops/feature)
        float w[5][7];
        #pragma unroll
        for (int jf = 0; jf < 7; jf++) {
            const float a = w1[((size_t)0 * HID + i) * 7 + jf];
            const float b = w1[((size_t)1 * HID + i) * 7 + jf];
            const float c = w1[((size_t)2 * HID + i) * 7 + jf];
            const float d = w1[((size_t)3 * HID + i) * 7 + jf];
            w[0][jf] = a + b + c + d;
            w[1][jf] = a - b + c - d;
            w[2][jf] = a - c;
            w[3][jf] = -a + b + c - d;
            w[4][jf] = a + b - c - d;
        }

        for (int r = 0; r < 16; r++) {
            float P[5] = {0.f, 0.f, 0.f, 0.f, 0.f};
            #pragma unroll
            for (int p = 0; p < 5; p++) {
                #pragma unroll
                for (int jf = 0; jf < 7; jf++)
                    P[p] += w[p][jf] * fp[r][p][jf];
            }
            const float yr = P[2] - P[4];
            const float yi = P[2] + P[3];
            const float e = P[0] + P[1], o = P[0] - P[1];
            const float y0 = 0.25f * (e + 2.f * yr) + bv;
            const float y1 = 0.25f * (o - 2.f * yi) + bv;
            const float y2 = 0.25f * (e - 2.f * yr) + bv;
            const float y3 = 0.25f * (o + 2.f * yi) + bv;
            const float r0 = fmaxf(y0, 0.f), r1 = fmaxf(y1, 0.f);
            const float r2 = fmaxf(y2, 0.f), r3 = fmaxf(y3, 0.f);
            const float zr = r0 - r2, zi = r3 - r1;
            const size_t off = (size_t)(row0 + r) * HID + i;
            g_act1[0 * PLANE + off] = __float2half(r0 + r1 + r2 + r3);
            g_act1[1 * PLANE + off] = __float2half(r0 - r1 + r2 - r3);
            g_act1[2 * PLANE + off] = __float2half(zr + zi);
            g_act1[3 * PLANE + off] = __float2half(zr);
            g_act1[4 * PLANE + off] = __float2half(zi);
        }
    }
}

__global__ void prep_kernel(const float* __restrict__ ins,
                            const float* __restrict__ w1,
                            const float* __restrict__ b1,
                            const float* __restrict__ w2,
                            const float* __restrict__ w3) {
    if (blockIdx.x < L1_BLOCKS) layer1_body(blockIdx.x, ins, w1, b1);
    else wprep_body(blockIdx.x - L1_BLOCKS, w1, w2, w3);
}

// ---------------- batched GEMM: C[j] = A[j] @ B[j]^T  (j = 0..4) ----------------
// R13-exact (frozen): R6 schedule + R10 fragment double buffering + R11
// coalesced smem-staged epilogue, fp16 output both layers.
static constexpr int GEMM_SMEM = 3 * 16384 * 2;  // 98304

template <int LAYER>
__global__ __launch_bounds__(256, 2)
void gemm_kernel() {
    constexpr int BK = 64;
    constexpr int KT = HID / BK;  // 32
    constexpr size_t BSTRIDE = (LAYER == 2) ? (size_t)HID * HID : (size_t)OUTD * HID;
    constexpr int CP = (LAYER == 2) ? HID : OUTD;

    extern __shared__ char smem[];
    const uint32_t sA = smem_u32(smem);            // [3][16KB]
    const uint32_t sB = sA + 3 * 16384;            // [3][16KB]

    const int tid = threadIdx.x;
    const int j = blockIdx.z;
    const int brow = blockIdx.y * 128;
    const int bcol = blockIdx.x * 128;

    const __half* Aall = (LAYER == 2) ? g_act1 : g_act2;
    const __half* Ball = (LAYER == 2) ? g_w2h : g_w3h;
    const char* Ag = (const char*)(Aall + (size_t)j * PLANE + (size_t)brow * HID);
    const char* Bg = (const char*)(Ball + (size_t)j * BSTRIDE + (size_t)bcol * HID);

    // loader mapping: thread t -> 16B group lg of rows lr0 + 32*i
    const int lg = tid & 7;
    const int lr0 = tid >> 3;

    auto issue = [&](int st, int kt) {
        const uint32_t dA = sA + st * 16384, dB = sB + st * 16384;
        const char* gA = Ag + (size_t)kt * 128;
        const char* gB = Bg + (size_t)kt * 128;
        #pragma unroll
        for (int i = 0; i < 4; i++) {
            const int r = lr0 + i * 32;
            const uint32_t ph = (uint32_t)r * 128 + (uint32_t)((lg ^ (r & 7)) * 16);
            cp16(dA + ph, gA + (size_t)r * (HID * 2) + lg * 16);
            cp16(dB + ph, gB + (size_t)r * (HID * 2) + lg * 16);
        }
        asm volatile("cp.async.commit_group;\n");
    };

    issue(0, 0);
    issue(1, 1);

    const int warp = tid >> 5, lane = tid & 31;
    const int wm = (warp >> 2) * 64;   // 2 warp rows
    const int wn = (warp & 3) * 32;    // 4 warp cols
    const int rl = (lane & 7) + (((lane >> 3) & 1) << 3);  // 0..15
    const int hs = (lane >> 4) & 1;
    const int sw = lane & 7;

    float acc[4][4][4];
    #pragma unroll
    for (int m = 0; m < 4; m++)
        #pragma unroll
        for (int n = 0; n < 4; n++)
            #pragma unroll
            for (int q = 0; q < 4; q++) acc[m][n][q] = 0.f;

    for (int kt = 0; kt < KT; kt++) {
        asm volatile("cp.async.wait_group 1;\n");
        __syncthreads();   // fences prev-iter readers of stage (kt+2)%3

        const int st = kt % 3;
        const uint32_t aBase = sA + st * 16384 + (uint32_t)(wm + rl) * 128;
        const uint32_t bBase = sB + st * 16384 + (uint32_t)(wn + rl) * 128;

        // double-buffered fragments across kk
        uint32_t af[2][4][4], bf[2][2][4];

        // preload kk = 0
        {
            const uint32_t goff = (uint32_t)((hs ^ sw) * 16);
            #pragma unroll
            for (int n2 = 0; n2 < 2; n2++)
                LDSM4(bf[0][n2][0], bf[0][n2][1], bf[0][n2][2], bf[0][n2][3],
                      bBase + n2 * 16 * 128 + goff);
            #pragma unroll
            for (int m = 0; m < 4; m++)
                LDSM4(af[0][m][0], af[0][m][1], af[0][m][2], af[0][m][3],
                      aBase + m * 16 * 128 + goff);
        }

        #pragma unroll
        for (int kk = 0; kk < 4; kk++) {
            const int cur = kk & 1, nxt = cur ^ 1;
            // prefetch kk+1 fragments BEFORE this kk's MMAs
            if (kk < 3) {
                const uint32_t goff = (uint32_t)((((kk + 1) * 2 + hs) ^ sw) * 16);
                #pragma unroll
                for (int n2 = 0; n2 < 2; n2++)
                    LDSM4(bf[nxt][n2][0], bf[nxt][n2][1], bf[nxt][n2][2], bf[nxt][n2][3],
                          bBase + n2 * 16 * 128 + goff);
                #pragma unroll
                for (int m = 0; m < 4; m++)
                    LDSM4(af[nxt][m][0], af[nxt][m][1], af[nxt][m][2], af[nxt][m][3],
                          aBase + m * 16 * 128 + goff);
            }
            #pragma unroll
            for (int m = 0; m < 4; m++) {
                #pragma unroll
                for (int n2 = 0; n2 < 2; n2++) {
                    mma16816(acc[m][n2 * 2 + 0], af[cur][m], bf[cur][n2][0], bf[cur][n2][2]);
                    mma16816(acc[m][n2 * 2 + 1], af[cur][m], bf[cur][n2][1], bf[cur][n2][3]);
                }
            }
            // combined issue+commit right after first kk block (R6-proven placement)
            if (kk == 0) {
                if (kt + 2 < KT) issue((kt + 2) % 3, kt + 2);
                else asm volatile("cp.async.commit_group;\n");
            }
        }
    }

    // ---- epilogue: stage C (fp16) through smem, then coalesced 16-B stores ----
    asm volatile("cp.async.wait_group 0;\n");   // drain tail copies into stage slots
    __syncthreads();                             // all warps done with mainloop smem

    const int r0 = lane >> 2, cql = (lane & 3) * 2;
    constexpr int PT = 136;                      // halves; 16B-aligned rows, +4 bank shift/row
    __half* sC = (__half*)smem;
    #pragma unroll
    for (int m = 0; m < 4; m++) {
        #pragma unroll
        for (int jn = 0; jn < 4; jn++) {
            const int rr = wm + m * 16 + r0;
            const int cc = wn + (jn >> 1) * 16 + (jn & 1) * 8 + cql;
            *(__half2*)&sC[(size_t)rr * PT + cc] =
                __floats2half2_rn(acc[m][jn][0], acc[m][jn][1]);
            *(__half2*)&sC[(size_t)(rr + 8) * PT + cc] =
                __floats2half2_rn(acc[m][jn][2], acc[m][jn][3]);
        }
    }
    __syncthreads();
    __half* C = (LAYER == 2) ? (g_pre2 + (size_t)j * PLANE)
                             : (g_out3h + (size_t)j * OPLANE);
    #pragma unroll
    for (int i = 0; i < 8; i++) {                // 2048 chunks of 16B / 256 thr
        const int idx = tid + i * 256;
        const int rr = idx >> 4;
        const int cc = (idx & 15) * 8;
        uint4 v = *(const uint4*)&sC[(size_t)rr * PT + cc];
        *(uint4*)&C[(size_t)(brow + rr) * CP + bcol + cc] = v;
    }
}

// ---------------- inverse DFT + bias + LN + relu + forward DFT ----------------
__global__ void ln_tf_kernel(const float* __restrict__ b2,
                             const float* __restrict__ lng,
                             const float* __restrict__ lnb) {
    const size_t rf = blockIdx.x;
    const int t = threadIdx.x;
    const size_t off = rf * HID;
    const int c0 = t * 8;

    float P[5][8];
    #pragma unroll
    for (int jp = 0; jp < 5; jp++) {
        float4 v = *((const float4*)(g_pre2 + jp * PLANE + off) + t);
        const __half2* h = (const __half2*)&v;
        #pragma unroll
        for (int k = 0; k < 4; k++) {
            float2 f = __half22float2(h[k]);
            P[jp][2 * k] = f.x;
            P[jp][2 * k + 1] = f.y;
        }
    }

    float bb[8];
    *(float4*)&bb[0] = *(const float4*)&b2[c0];
    *(float4*)&bb[4] = *(const float4*)&b2[c0 + 4];

    float y[4][8];
    float s[4] = {0.f, 0.f, 0.f, 0.f}, q[4] = {0.f, 0.f, 0.f, 0.f};
    #pragma unroll
    for (int k = 0; k < 8; k++) {
        const float yr = P[2][k] - P[4][k];
        const float yi = P[2][k] + P[3][k];
        const float e = P[0][k] + P[1][k], o = P[0][k] - P[1][k];
        y[0][k] = 0.25f * (e + 2.f * yr) + bb[k];
        y[1][k] = 0.25f * (o - 2.f * yi) + bb[k];
        y[2][k] = 0.25f * (e - 2.f * yr) + bb[k];
        y[3][k] = 0.25f * (o + 2.f * yi) + bb[k];
        #pragma unroll
        for (int g = 0; g < 4; g++) { s[g] += y[g][k]; q[g] += y[g][k] * y[g][k]; }
    }

    __shared__ float ss[4][8], qq[4][8];
    const int warp = t >> 5, lane = t & 31;
    #pragma unroll
    for (int g = 0; g < 4; g++) {
        #pragma unroll
        for (int o = 16; o > 0; o >>= 1) {
            s[g] += __shfl_down_sync(0xffffffffu, s[g], o);
            q[g] += __shfl_down_sync(0xffffffffu, q[g], o);
        }
        if (lane == 0) { ss[g][warp] = s[g]; qq[g][warp] = q[g]; }
    }
    __syncthreads();
    __shared__ float mean[4], rstd[4];
    if (t < 4) {
        float a = 0.f, b = 0.f;
        #pragma unroll
        for (int w = 0; w < 8; w++) { a += ss[t][w]; b += qq[t][w]; }
        const float m = a * (1.f / HID);
        mean[t] = m;
        rstd[t] = rsqrtf(b * (1.f / HID) - m * m + 1e-5f);
    }
    __syncthreads();

    float gv[8], bv[8];
    *(float4*)&gv[0] = *(const float4*)&lng[c0];
    *(float4*)&gv[4] = *(const float4*)&lng[c0 + 4];
    *(float4*)&bv[0] = *(const float4*)&lnb[c0];
    *(float4*)&bv[4] = *(const float4*)&lnb[c0 + 4];

    float r[4][8];
    #pragma unroll
    for (int k = 0; k < 8; k++) {
        #pragma unroll
        for (int g = 0; g < 4; g++)
            r[g][k] = fmaxf((y[g][k] - mean[g]) * rstd[g] * gv[k] + bv[k], 0.f);
    }

    float Z[5][8];
    #pragma unroll
    for (int k = 0; k < 8; k++) {
        const float zr = r[0][k] - r[2][k], zi = r[3][k] - r[1][k];
        Z[0][k] = r[0][k] + r[1][k] + r[2][k] + r[3][k];
        Z[1][k] = r[0][k] - r[1][k] + r[2][k] - r[3][k];
        Z[2][k] = zr + zi;
        Z[3][k] = zr;
        Z[4][k] = zi;
    }
    #pragma unroll
    for (int jp = 0; jp < 5; jp++) {
        float4 v;
        __half2* h = (__half2*)&v;
        #pragma unroll
        for (int k = 0; k < 4; k++)
            h[k] = __floats2half2_rn(Z[jp][2 * k], Z[jp][2 * k + 1]);
        *((float4*)(g_act2 + jp * PLANE + off) + t) = v;
    }
}

// ---------------- final: inverse DFT + bias b3 -> out (2 rows per CTA) ----------------
__global__ void combine3_kernel(const float* __restrict__ b3, float* __restrict__ out) {
    const size_t row0 = (size_t)blockIdx.x * 2;
    const int t = threadIdx.x;
    const int g = t >> 6;
    const int c0 = (t & 63) * 8;

    #pragma unroll
    for (int rr = 0; rr < 2; rr++) {
        const size_t row = row0 + rr;
        const size_t poff = row * OUTD + c0;
        float P[5][8];
        #pragma unroll
        for (int jp = 0; jp < 5; jp++) {
            uint4 v = *(const uint4*)(g_out3h + (size_t)jp * OPLANE + poff);
            const __half2* h = (const __half2*)&v;
            #pragma unroll
            for (int k = 0; k < 4; k++) {
                float2 f = __half22float2(h[k]);
                P[jp][2 * k] = f.x;
                P[jp][2 * k + 1] = f.y;
            }
        }
        float o[8];
        #pragma unroll
        for (int k = 0; k < 8; k++) {
            const float yr = P[2][k] - P[4][k];
            const float yi = P[2][k] + P[3][k];
            const float e = P[0][k] + P[1][k], od = P[0][k] - P[1][k];
            float v;
            if (g == 0)      v = 0.25f * (e + 2.f * yr);
            else if (g == 1) v = 0.25f * (od - 2.f * yi);
            else if (g == 2) v = 0.25f * (e - 2.f * yr);
            else             v = 0.25f * (od + 2.f * yi);
            o[k] = v + __ldg(&b3[c0 + k]);
        }
        float* dst = out + row * 2048 + (size_t)g * OUTD + c0;
        *(float4*)&dst[0] = *(const float4*)&o[0];
        *(float4*)&dst[4] = *(const float4*)&o[4];
    }
}

// ---------------- launch ----------------
extern "C" void kernel_launch(void* const* d_in, const int* in_sizes, int n_in,
                              void* d_out, int out_size) {
    const float* ins = (const float*)d_in[0];
    const float* w1 = (const float*)d_in[1];
    const float* b1 = (const float*)d_in[2];
    const float* w2 = (const float*)d_in[3];
    const float* b2 = (const float*)d_in[4];
    const float* w3 = (const float*)d_in[5];
    const float* b3 = (const float*)d_in[6];
    const float* lng = (const float*)d_in[7];
    const float* lnb = (const float*)d_in[8];
    float* out = (float*)d_out;

    cudaFuncSetAttribute(gemm_kernel<2>, cudaFuncAttributeMaxDynamicSharedMemorySize, GEMM_SMEM);
    cudaFuncSetAttribute(gemm_kernel<3>, cudaFuncAttributeMaxDynamicSharedMemorySize, GEMM_SMEM);

    prep_kernel<<<L1_BLOCKS + WP_BLOCKS, 256>>>(ins, w1, b1, w2, w3);

    {
        dim3 grid(HID / 128, BROWS / 128, 5);   // (16, 80, 5)
        gemm_kernel<2><<<grid, 256, GEMM_SMEM>>>();
    }
    ln_tf_kernel<<<BROWS, 256>>>(b2, lng, lnb);
    {
        dim3 grid(OUTD / 128, BROWS / 128, 5);  // (4, 80, 5)
        gemm_kernel<3><<<grid, 256, GEMM_SMEM>>>();
    }
    combine3_kernel<<<BROWS / 2, 256>>>(b3, out);
}